// round 12
// baseline (speedup 1.0000x reference)
#include <cuda_runtime.h>
#include <cuda_bf16.h>
#include <cstdint>

#define BB 32
#define NNODE 8192
#define DDIM 8
#define PPART 64
#define WWID 128
#define TTEMP 8
#define LL2 32
#define I2D 2320
#define KDIM 1024

// scratch (no allocs allowed)
__device__ __align__(256) float g_base[PPART * I2D];                // b1 + cap@W2
__device__ __align__(256) float g_h[(size_t)PPART * BB * I2D];      // h as [p][b][o]
__device__ __align__(256) float g_zp[PPART * 8 * BB * WWID];        // split-K partials
__device__ __align__(256) float g_wx[BB * PPART * DDIM];            // [b][p][d]

// ---------------- helpers ----------------
__device__ __forceinline__ unsigned long long ffma2(unsigned long long a,
                                                    unsigned long long b,
                                                    unsigned long long c) {
    unsigned long long d;
    asm("fma.rn.f32x2 %0, %1, %2, %3;" : "=l"(d) : "l"(a), "l"(b), "l"(c));
    return d;
}
__device__ __forceinline__ float flo(unsigned long long v) { return __uint_as_float((unsigned)v); }
__device__ __forceinline__ float fhi(unsigned long long v) { return __uint_as_float((unsigned)(v >> 32)); }
__device__ __forceinline__ void cp16(uint32_t dst, const void* src, int szb) {
    asm volatile("cp.async.cg.shared.global [%0], [%1], 16, %2;\n" :: "r"(dst), "l"(src), "r"(szb));
}
__device__ __forceinline__ void cp_commit() { asm volatile("cp.async.commit_group;\n"); }
__device__ __forceinline__ void cp_wait1()  { asm volatile("cp.async.wait_group 1;\n"); }

#define LDS64(vx, vy, addr) \
    asm volatile("ld.shared.v2.f32 {%0,%1}, [%2];" : "=f"(vx), "=f"(vy) : "r"(addr))

#define MMA16816(d, a0, a1, a2, a3, b0, b1) \
    asm volatile("mma.sync.aligned.m16n8k16.row.col.f32.bf16.bf16.f32 " \
                 "{%0,%1,%2,%3}, {%4,%5,%6,%7}, {%8,%9}, {%0,%1,%2,%3};" \
                 : "+f"((d)[0]), "+f"((d)[1]), "+f"((d)[2]), "+f"((d)[3]) \
                 : "r"(a0), "r"(a1), "r"(a2), "r"(a3), "r"(b0), "r"(b1))

// split two fp32 (k, k+1) into bf16x2 hi (lo-lane=vx) and bf16x2 residual
__device__ __forceinline__ void bfsplit(float vx, float vy, uint32_t& h, uint32_t& l) {
    asm("cvt.rn.bf16x2.f32 %0, %1, %2;" : "=r"(h) : "f"(vy), "f"(vx));
    float hx = __uint_as_float(h << 16);
    float hy = __uint_as_float(h & 0xffff0000u);
    float lx = vx - hx, ly = vy - hy;
    asm("cvt.rn.bf16x2.f32 %0, %1, %2;" : "=r"(l) : "f"(ly), "f"(lx));
}

// ========== dummy (profiling slot shifter) ==========
__global__ void k_nop() {}

// ========== kernel 1: base[p,o] = b1 + cap(p)·W2[p,o,:] ==========
__global__ void k_base(const float* __restrict__ W2, const float* __restrict__ b1,
                       const float* __restrict__ cap) {
    int idx = blockIdx.x * 8 + (threadIdx.x >> 5);
    if (idx >= PPART * I2D) return;
    int p = idx / I2D, lane = threadIdx.x & 31;
    float4 wv = *(const float4*)(W2 + (size_t)idx * WWID + lane * 4);
    float4 cv = *(const float4*)(cap + p * WWID + lane * 4);
    float acc = wv.x * cv.x + wv.y * cv.y + wv.z * cv.z + wv.w * cv.w;
    #pragma unroll
    for (int o = 16; o > 0; o >>= 1) acc += __shfl_xor_sync(0xffffffffu, acc, o);
    if (lane == 0) g_base[idx] = acc + b1[idx];
}

// ========== kernel 2: h = W0 x xg. cp.async fp32 staging + bf16 k16 3-pass MMA ==========
#define APITCH 40                          // floats per row: LDS.64 bank = 8g+2t, conflict-free
#define BOFFT (128 * APITCH)               // B after 128 A rows
#define STAGEF (160 * APITCH)              // 6400 floats = 25600 B per stage

__global__ void __launch_bounds__(128, 4)
k_main_bf16s(const float* __restrict__ W0, const float* __restrict__ x,
             const float* __restrict__ t, const float* __restrict__ W1,
             const int* __restrict__ nodes) {
    const int p = blockIdx.y, m0 = blockIdx.x * 128;
    const int tid = threadIdx.x, w = tid >> 5, lane = tid & 31;
    extern __shared__ float sm[];
    __shared__ float s_t[BB * 9];
    __shared__ int s_nodes[WWID];
    const uint32_t smb = (uint32_t)__cvta_generic_to_shared(sm);

    for (int i = tid; i < BB * TTEMP; i += 128) s_t[(i >> 3) * 9 + (i & 7)] = t[i];
    if (tid < WWID) s_nodes[tid] = nodes[p * WWID + tid];
    __syncthreads();

    const int lrow = lane >> 3, akk = (lane & 7) * 4;
    const float* W0p = W0 + (size_t)p * I2D * KDIM;

    auto loadA = [&](int c, int buf) {
        int k0 = c * 32;
        #pragma unroll
        for (int i = 0; i < 8; i++) {
            int row = w * 32 + i * 4 + lrow;
            int m = m0 + row;
            m = (m < I2D) ? m : (I2D - 1);
            cp16(smb + (uint32_t)(buf * STAGEF + row * APITCH + akk) * 4,
                 W0p + (size_t)m * KDIM + k0 + akk, 16);
        }
    };
    auto loadB = [&](int c, int buf) {
        int k0 = c * 32;
        #pragma unroll
        for (int i = 0; i < 2; i++) {
            int b = w * 8 + i * 4 + lrow;
            int kk = k0 + akk;
            int node = s_nodes[kk >> 3];
            cp16(smb + (uint32_t)(buf * STAGEF + BOFFT + b * APITCH + akk) * 4,
                 x + (size_t)b * (NNODE * DDIM) + (size_t)node * DDIM + (kk & 7), 16);
        }
    };

    float acc[2][4][4];
    #pragma unroll
    for (int i = 0; i < 2; i++)
        #pragma unroll
        for (int j = 0; j < 4; j++)
            #pragma unroll
            for (int r = 0; r < 4; r++) acc[i][j][r] = 0.f;

    loadA(0, 0); loadB(0, 0); cp_commit();
    loadA(1, 1); loadB(1, 1); cp_commit();

    // fragment bases: g = lane>>2 (row / n), tig = lane&3 (k pair)
    const int g = lane >> 2, tig = lane & 3;
    const uint32_t a_base = smb + (uint32_t)((w * 32 + g) * APITCH + 2 * tig) * 4;
    const uint32_t b_base = smb + (uint32_t)(BOFFT + g * APITCH + 2 * tig) * 4;
    const uint32_t R8 = 8 * APITCH * 4;    // +8 rows
    const uint32_t R16 = 16 * APITCH * 4;  // +16 rows

    for (int c = 0; c < 32; c++) {
        cp_wait1();
        __syncthreads();
        const uint32_t bsel = (uint32_t)(c & 1) * (STAGEF * 4);

        #pragma unroll
        for (int ks = 0; ks < 2; ks++) {
            const uint32_t ko = (uint32_t)ks * 64;  // 16 floats per kstep
            // B fragments: 4 n-blocks, each b0 (k=2tig,+1) and b1 (k=2tig+8,+9)
            uint32_t bh[4][2], bl[4][2];
            #pragma unroll
            for (int j = 0; j < 4; j++) {
                uint32_t ba = b_base + bsel + (uint32_t)j * R8 + ko;
                float v0x, v0y, v1x, v1y;
                LDS64(v0x, v0y, ba);
                LDS64(v1x, v1y, ba + 32);
                bfsplit(v0x, v0y, bh[j][0], bl[j][0]);
                bfsplit(v1x, v1y, bh[j][1], bl[j][1]);
            }
            #pragma unroll
            for (int i = 0; i < 2; i++) {
                uint32_t aa = a_base + bsel + (uint32_t)i * R16 + ko;
                float v0x, v0y, v1x, v1y, v2x, v2y, v3x, v3y;
                LDS64(v0x, v0y, aa);             // row g,   k=2tig,+1
                LDS64(v1x, v1y, aa + R8);        // row g+8
                LDS64(v2x, v2y, aa + 32);        // row g,   k=2tig+8,+9
                LDS64(v3x, v3y, aa + R8 + 32);   // row g+8
                uint32_t ah0, ah1, ah2, ah3, al0, al1, al2, al3;
                bfsplit(v0x, v0y, ah0, al0);
                bfsplit(v1x, v1y, ah1, al1);
                bfsplit(v2x, v2y, ah2, al2);
                bfsplit(v3x, v3y, ah3, al3);
                #pragma unroll
                for (int j = 0; j < 4; j++) {
                    MMA16816(acc[i][j], ah0, ah1, ah2, ah3, bh[j][0], bh[j][1]);
                    MMA16816(acc[i][j], ah0, ah1, ah2, ah3, bl[j][0], bl[j][1]);
                    MMA16816(acc[i][j], al0, al1, al2, al3, bh[j][0], bh[j][1]);
                }
            }
        }
        __syncthreads();
        if (c + 2 < 32) { loadA(c + 2, c & 1); loadB(c + 2, c & 1); }
        cp_commit();
    }

    // ---- epilogue: + base + W1·t, leaky 0.01 -> g_h[p][b][o] ----
    const int tc = lane & 3;
    #pragma unroll
    for (int i = 0; i < 2; i++) {
        #pragma unroll
        for (int r = 0; r < 2; r++) {
            int o = m0 + w * 32 + i * 16 + r * 8 + g;
            if (o >= I2D) continue;
            float bs = g_base[p * I2D + o];
            const float* w1r = W1 + (size_t)(p * I2D + o) * TTEMP;
            float4 wa = *(const float4*)(w1r);
            float4 wb = *(const float4*)(w1r + 4);
            #pragma unroll
            for (int j = 0; j < 4; j++) {
                #pragma unroll
                for (int cc = 0; cc < 2; cc++) {
                    int b = j * 8 + tc * 2 + cc;
                    const float* tb = s_t + b * 9;
                    float v = acc[i][j][r * 2 + cc] + bs;
                    v += wa.x * tb[0] + wa.y * tb[1] + wa.z * tb[2] + wa.w * tb[3]
                       + wb.x * tb[4] + wb.y * tb[5] + wb.z * tb[6] + wb.w * tb[7];
                    v = v > 0.f ? v : 0.01f * v;
                    g_h[(size_t)(p * BB + b) * I2D + o] = v;
                }
            }
        }
    }
}

// ========== kernel 3: z partials, split-K x 8 (SIMT f32x2, unchanged/passing) ==========
#define ZPITCH 36
#define ZABUF  (128 * ZPITCH)
#define ZBOFF  (2 * ZABUF)
#define ZBBUF  (32 * ZPITCH)
#define ZSMEMF (ZBOFF + 2 * ZBBUF)

__global__ void __launch_bounds__(128, 3)
k_z(const float* __restrict__ W3) {
    const int s = blockIdx.x, p = blockIdx.y, tid = threadIdx.x;
    const int kbase = s * 288;
    const int kend = (s == 7) ? I2D : (kbase + 288);
    const int NCH = (s == 7) ? 10 : 9;
    __shared__ __align__(16) float smz[ZSMEMF];
    const uint32_t smaddr = (uint32_t)__cvta_generic_to_shared(smz);

    const int lane = tid & 31, wrp = tid >> 5;
    const int lrow = lane >> 3, akk = (lane & 7) * 4;
    const float* W3p = W3 + (size_t)p * WWID * I2D;
    const float* Hp = g_h + (size_t)p * BB * I2D;

    auto ldrow = [&](const float* basep, int row, int c, uint32_t doff) {
        int kk = kbase + c * 32 + akk;
        int vb = (kend - kk) * 4; vb = vb < 0 ? 0 : (vb > 16 ? 16 : vb);
        int kc = kk <= (I2D - 4) ? kk : (I2D - 4);
        cp16(smaddr + doff * 4, basep + (size_t)row * I2D + kc, vb);
    };
    auto loadA = [&](int c, int buf) {
        #pragma unroll
        for (int i = 0; i < 8; i++) {
            int row = wrp * 32 + i * 4 + lrow;
            ldrow(W3p, row, c, (uint32_t)(buf * ZABUF + row * ZPITCH + akk));
        }
    };
    auto loadB = [&](int c, int buf) {
        #pragma unroll
        for (int i = 0; i < 2; i++) {
            int b = wrp * 8 + i * 4 + lrow;
            ldrow(Hp, b, c, (uint32_t)(ZBOFF + buf * ZBBUF + b * ZPITCH + akk));
        }
    };

    unsigned long long acc[8][4];
    #pragma unroll
    for (int i = 0; i < 8; i++)
        #pragma unroll
        for (int j = 0; j < 4; j++) acc[i][j] = 0ull;

    loadA(0, 0); loadB(0, 0); cp_commit();
    loadA(1, 1); loadB(1, 1); cp_commit();

    const int tm = tid >> 3, tn = tid & 7;
    for (int c = 0; c < NCH; c++) {
        cp_wait1();
        __syncthreads();
        const unsigned long long* Ap = (const unsigned long long*)(smz + (c & 1) * ZABUF);
        const unsigned long long* Bp = (const unsigned long long*)(smz + ZBOFF + (c & 1) * ZBBUF);
        #pragma unroll
        for (int kp = 0; kp < 16; kp++) {
            unsigned long long av[8], bv[4];
            #pragma unroll
            for (int i = 0; i < 8; i++) av[i] = Ap[(tm + i * 16) * (ZPITCH / 2) + kp];
            #pragma unroll
            for (int j = 0; j < 4; j++) bv[j] = Bp[(tn + j * 8) * (ZPITCH / 2) + kp];
            #pragma unroll
            for (int i = 0; i < 8; i++)
                #pragma unroll
                for (int j = 0; j < 4; j++) acc[i][j] = ffma2(av[i], bv[j], acc[i][j]);
        }
        __syncthreads();
        if (c + 2 < NCH) { loadA(c + 2, c & 1); loadB(c + 2, c & 1); }
        cp_commit();
    }

    float* zp = g_zp + (size_t)(p * 8 + s) * BB * WWID;
    #pragma unroll
    for (int i = 0; i < 8; i++) {
        int ww = tm + i * 16;
        #pragma unroll
        for (int j = 0; j < 4; j++) {
            int b = tn + j * 8;
            zp[b * WWID + ww] = flo(acc[i][j]) + fhi(acc[i][j]);
        }
    }
}

// ========== kernel 4: reduce partials + bias + relu + weighted gather ==========
__global__ void k_wx(const float* __restrict__ x, const float* __restrict__ b3) {
    const int p = blockIdx.x, b = blockIdx.y, w = threadIdx.x;
    const int lane = w & 31, wrp = w >> 5;
    __shared__ float red[32];
    float z = b3[p * WWID + w];
    #pragma unroll
    for (int s = 0; s < 8; s++)
        z += g_zp[((size_t)(p * 8 + s) * BB + b) * WWID + w];
    z = z > 0.f ? z : 0.f;
    const float4* xr = (const float4*)(x + ((size_t)b * NNODE + p * WWID + w) * DDIM);
    float4 xa = xr[0], xb = xr[1];
    float v[8] = {z * xa.x, z * xa.y, z * xa.z, z * xa.w,
                  z * xb.x, z * xb.y, z * xb.z, z * xb.w};
    #pragma unroll
    for (int d = 0; d < 8; d++)
        #pragma unroll
        for (int o = 16; o > 0; o >>= 1) v[d] += __shfl_xor_sync(0xffffffffu, v[d], o);
    if (lane < 8) red[wrp * 8 + lane] = v[lane];
    __syncthreads();
    if (w < 8)
        g_wx[((size_t)b * PPART + p) * DDIM + w] =
            red[w] + red[8 + w] + red[16 + w] + red[24 + w];
}

// ========== kernel 5: conv + leaky 0.02 ==========
__global__ void k_y(const float* __restrict__ cw, const float* __restrict__ cb,
                    float* __restrict__ out) {
    const int b = blockIdx.x, l = threadIdx.x;
    const float* wxb = g_wx + (size_t)b * PPART * DDIM;
    float acc = cb[l];
    #pragma unroll 4
    for (int p = 0; p < PPART; p++)
        #pragma unroll
        for (int d = 0; d < 8; d++)
            acc += wxb[p * DDIM + d] * cw[l * (DDIM * PPART) + d * PPART + p];
    out[b * LL2 + l] = acc > 0.f ? acc : 0.02f * acc;
}

extern "C" void kernel_launch(void* const* d_in, const int* in_sizes, int n_in,
                              void* d_out, int out_size) {
    const float* x    = (const float*)d_in[0];
    const float* t    = (const float*)d_in[1];
    const float* cap  = (const float*)d_in[2];
    // d_in[3] = partition_index (identity; folded into k_wx)
    const float* W0   = (const float*)d_in[4];
    const float* W1   = (const float*)d_in[5];
    const float* b1   = (const float*)d_in[6];
    const float* W2   = (const float*)d_in[7];
    const float* W3   = (const float*)d_in[8];
    const float* b3   = (const float*)d_in[9];
    const float* cw   = (const float*)d_in[10];
    const float* cb   = (const float*)d_in[11];
    const int* nodes  = (const int*)d_in[12];
    float* out = (float*)d_out;

    const int dsm = 2 * STAGEF * 4;   // 51200 B
    cudaFuncSetAttribute(k_main_bf16s, cudaFuncAttributeMaxDynamicSharedMemorySize, dsm);

    // two no-op launches keep k_main in the ncu capture slot
    k_nop<<<1, 32>>>();
    k_nop<<<1, 32>>>();
    k_base<<<(PPART * I2D + 7) / 8, 256>>>(W2, b1, cap);
    k_main_bf16s<<<dim3(19, PPART), 128, dsm>>>(W0, x, t, W1, nodes);
    k_z<<<dim3(8, PPART), 128>>>(W3);
    k_wx<<<dim3(PPART, BB), 128>>>(x, b3);
    k_y<<<BB, LL2>>>(cw, cb, out);
}

// round 13
// speedup vs baseline: 1.1475x; 1.1475x over previous
#include <cuda_runtime.h>
#include <cuda_bf16.h>
#include <cstdint>

#define BB 32
#define NNODE 8192
#define DDIM 8
#define PPART 64
#define WWID 128
#define TTEMP 8
#define LL2 32
#define I2D 2320
#define KDIM 1024

// scratch (no allocs allowed)
__device__ __align__(256) float g_base[PPART * I2D];                // b1 + cap@W2
__device__ __align__(256) float g_h[(size_t)PPART * BB * I2D];      // h as [p][b][o]
__device__ __align__(256) float g_zp[PPART * 8 * BB * WWID];        // split-K partials
__device__ __align__(256) float g_wx[BB * PPART * DDIM];            // [b][p][d]

// ---------------- helpers ----------------
__device__ __forceinline__ void cp16(uint32_t dst, const void* src, int szb) {
    asm volatile("cp.async.cg.shared.global [%0], [%1], 16, %2;\n" :: "r"(dst), "l"(src), "r"(szb));
}
__device__ __forceinline__ void cp_commit() { asm volatile("cp.async.commit_group;\n"); }
__device__ __forceinline__ void cp_wait1()  { asm volatile("cp.async.wait_group 1;\n"); }

#define LDS64(vx, vy, addr) \
    asm volatile("ld.shared.v2.f32 {%0,%1}, [%2];" : "=f"(vx), "=f"(vy) : "r"(addr))

#define MMA16816(d, a0, a1, a2, a3, b0, b1) \
    asm volatile("mma.sync.aligned.m16n8k16.row.col.f32.bf16.bf16.f32 " \
                 "{%0,%1,%2,%3}, {%4,%5,%6,%7}, {%8,%9}, {%0,%1,%2,%3};" \
                 : "+f"((d)[0]), "+f"((d)[1]), "+f"((d)[2]), "+f"((d)[3]) \
                 : "r"(a0), "r"(a1), "r"(a2), "r"(a3), "r"(b0), "r"(b1))

// split two fp32 (k, k+1) into bf16x2 hi (lo-lane=vx) and bf16x2 residual
__device__ __forceinline__ void bfsplit(float vx, float vy, uint32_t& h, uint32_t& l) {
    asm("cvt.rn.bf16x2.f32 %0, %1, %2;" : "=r"(h) : "f"(vy), "f"(vx));
    float hx = __uint_as_float(h << 16);
    float hy = __uint_as_float(h & 0xffff0000u);
    float lx = vx - hx, ly = vy - hy;
    asm("cvt.rn.bf16x2.f32 %0, %1, %2;" : "=r"(l) : "f"(ly), "f"(lx));
}

// ========== kernel 1: base[p,o] = b1 + cap(p)·W2[p,o,:] ==========
__global__ void k_base(const float* __restrict__ W2, const float* __restrict__ b1,
                       const float* __restrict__ cap) {
    int idx = blockIdx.x * 8 + (threadIdx.x >> 5);
    if (idx >= PPART * I2D) return;
    int p = idx / I2D, lane = threadIdx.x & 31;
    float4 wv = *(const float4*)(W2 + (size_t)idx * WWID + lane * 4);
    float4 cv = *(const float4*)(cap + p * WWID + lane * 4);
    float acc = wv.x * cv.x + wv.y * cv.y + wv.z * cv.z + wv.w * cv.w;
    #pragma unroll
    for (int o = 16; o > 0; o >>= 1) acc += __shfl_xor_sync(0xffffffffu, acc, o);
    if (lane == 0) g_base[idx] = acc + b1[idx];
}

// ========== shared geometry for MMA kernels ==========
#define APITCH 40                          // floats per row: LDS.64 conflict-free
#define BOFFT (128 * APITCH)               // B after 128 A rows
#define STAGEF (160 * APITCH)              // 6400 floats = 25600 B per stage

// ========== kernel 2: h = W0 x xg. cp.async fp32 staging + bf16 k16 3-pass MMA ==========
__global__ void __launch_bounds__(128, 3)
k_main_bf16s(const float* __restrict__ W0, const float* __restrict__ x,
             const float* __restrict__ t, const float* __restrict__ W1,
             const int* __restrict__ nodes) {
    const int p = blockIdx.y, m0 = blockIdx.x * 128;
    const int tid = threadIdx.x, w = tid >> 5, lane = tid & 31;
    extern __shared__ float sm[];
    __shared__ float s_t[BB * 9];
    __shared__ int s_nodes[WWID];
    const uint32_t smb = (uint32_t)__cvta_generic_to_shared(sm);

    for (int i = tid; i < BB * TTEMP; i += 128) s_t[(i >> 3) * 9 + (i & 7)] = t[i];
    if (tid < WWID) s_nodes[tid] = nodes[p * WWID + tid];
    __syncthreads();

    const int lrow = lane >> 3, akk = (lane & 7) * 4;
    const float* W0p = W0 + (size_t)p * I2D * KDIM;

    auto loadA = [&](int c, int buf) {
        int k0 = c * 32;
        #pragma unroll
        for (int i = 0; i < 8; i++) {
            int row = w * 32 + i * 4 + lrow;
            int m = m0 + row;
            m = (m < I2D) ? m : (I2D - 1);
            cp16(smb + (uint32_t)(buf * STAGEF + row * APITCH + akk) * 4,
                 W0p + (size_t)m * KDIM + k0 + akk, 16);
        }
    };
    auto loadB = [&](int c, int buf) {
        int k0 = c * 32;
        #pragma unroll
        for (int i = 0; i < 2; i++) {
            int b = w * 8 + i * 4 + lrow;
            int kk = k0 + akk;
            int node = s_nodes[kk >> 3];
            cp16(smb + (uint32_t)(buf * STAGEF + BOFFT + b * APITCH + akk) * 4,
                 x + (size_t)b * (NNODE * DDIM) + (size_t)node * DDIM + (kk & 7), 16);
        }
    };

    float acc[2][4][4];
    #pragma unroll
    for (int i = 0; i < 2; i++)
        #pragma unroll
        for (int j = 0; j < 4; j++)
            #pragma unroll
            for (int r = 0; r < 4; r++) acc[i][j][r] = 0.f;

    loadA(0, 0); loadB(0, 0); cp_commit();
    loadA(1, 1); loadB(1, 1); cp_commit();

    const int g = lane >> 2, tig = lane & 3;
    const uint32_t a_base = smb + (uint32_t)((w * 32 + g) * APITCH + 2 * tig) * 4;
    const uint32_t b_base = smb + (uint32_t)(BOFFT + g * APITCH + 2 * tig) * 4;
    const uint32_t R8 = 8 * APITCH * 4;
    const uint32_t R16 = 16 * APITCH * 4;

    for (int c = 0; c < 32; c++) {
        cp_wait1();
        __syncthreads();
        const uint32_t bsel = (uint32_t)(c & 1) * (STAGEF * 4);

        #pragma unroll
        for (int ks = 0; ks < 2; ks++) {
            const uint32_t ko = (uint32_t)ks * 64;
            uint32_t bh[4][2], bl[4][2];
            #pragma unroll
            for (int j = 0; j < 4; j++) {
                uint32_t ba = b_base + bsel + (uint32_t)j * R8 + ko;
                float v0x, v0y, v1x, v1y;
                LDS64(v0x, v0y, ba);
                LDS64(v1x, v1y, ba + 32);
                bfsplit(v0x, v0y, bh[j][0], bl[j][0]);
                bfsplit(v1x, v1y, bh[j][1], bl[j][1]);
            }
            #pragma unroll
            for (int i = 0; i < 2; i++) {
                uint32_t aa = a_base + bsel + (uint32_t)i * R16 + ko;
                float v0x, v0y, v1x, v1y, v2x, v2y, v3x, v3y;
                LDS64(v0x, v0y, aa);
                LDS64(v1x, v1y, aa + R8);
                LDS64(v2x, v2y, aa + 32);
                LDS64(v3x, v3y, aa + R8 + 32);
                uint32_t ah0, ah1, ah2, ah3, al0, al1, al2, al3;
                bfsplit(v0x, v0y, ah0, al0);
                bfsplit(v1x, v1y, ah1, al1);
                bfsplit(v2x, v2y, ah2, al2);
                bfsplit(v3x, v3y, ah3, al3);
                #pragma unroll
                for (int j = 0; j < 4; j++) {
                    MMA16816(acc[i][j], ah0, ah1, ah2, ah3, bh[j][0], bh[j][1]);
                    MMA16816(acc[i][j], ah0, ah1, ah2, ah3, bl[j][0], bl[j][1]);
                    MMA16816(acc[i][j], al0, al1, al2, al3, bh[j][0], bh[j][1]);
                }
            }
        }
        __syncthreads();
        if (c + 2 < 32) { loadA(c + 2, c & 1); loadB(c + 2, c & 1); }
        cp_commit();
    }

    // ---- epilogue: + base + W1·t, leaky 0.01 -> g_h[p][b][o] ----
    const int tc = lane & 3;
    #pragma unroll
    for (int i = 0; i < 2; i++) {
        #pragma unroll
        for (int r = 0; r < 2; r++) {
            int o = m0 + w * 32 + i * 16 + r * 8 + g;
            if (o >= I2D) continue;
            float bs = g_base[p * I2D + o];
            const float* w1r = W1 + (size_t)(p * I2D + o) * TTEMP;
            float4 wa = *(const float4*)(w1r);
            float4 wb = *(const float4*)(w1r + 4);
            #pragma unroll
            for (int j = 0; j < 4; j++) {
                #pragma unroll
                for (int cc = 0; cc < 2; cc++) {
                    int b = j * 8 + tc * 2 + cc;
                    const float* tb = s_t + b * 9;
                    float v = acc[i][j][r * 2 + cc] + bs;
                    v += wa.x * tb[0] + wa.y * tb[1] + wa.z * tb[2] + wa.w * tb[3]
                       + wb.x * tb[4] + wb.y * tb[5] + wb.z * tb[6] + wb.w * tb[7];
                    v = v > 0.f ? v : 0.01f * v;
                    g_h[(size_t)(p * BB + b) * I2D + o] = v;
                }
            }
        }
    }
}

// ========== kernel 3: z partials via bf16 3-pass MMA, split-K x 8 ==========
// zp[p][s][b][w] = sum_{o in slice s} W3[p][w][o] * h[p][b][o]
// slice s: 9 chunks of 32 (288 floats); s==7: 10 chunks, tail zero-filled by cp.async
__global__ void __launch_bounds__(128, 3)
k_z_mma(const float* __restrict__ W3) {
    const int s = blockIdx.x, p = blockIdx.y;
    const int tid = threadIdx.x, w = tid >> 5, lane = tid & 31;
    const int kbase = s * 288;
    const int NCH = (s == 7) ? 10 : 9;
    extern __shared__ float sm[];
    const uint32_t smb = (uint32_t)__cvta_generic_to_shared(sm);

    const int lrow = lane >> 3, akk = (lane & 7) * 4;
    const float* W3p = W3 + (size_t)p * WWID * I2D;
    const float* Hp = g_h + (size_t)p * BB * I2D;

    auto ldrow = [&](const float* basep, int row, int c, uint32_t doff) {
        int kk = kbase + c * 32 + akk;
        int vb = (I2D - kk) * 4; vb = vb < 0 ? 0 : (vb > 16 ? 16 : vb);
        int kc = kk <= (I2D - 4) ? kk : (I2D - 4);     // 16B-aligned clamp
        cp16(smb + doff * 4, basep + (size_t)row * I2D + kc, vb);  // zero-fills tail
    };
    auto loadA = [&](int c, int buf) {
        #pragma unroll
        for (int i = 0; i < 8; i++) {
            int row = w * 32 + i * 4 + lrow;
            ldrow(W3p, row, c, (uint32_t)(buf * STAGEF + row * APITCH + akk));
        }
    };
    auto loadB = [&](int c, int buf) {
        #pragma unroll
        for (int i = 0; i < 2; i++) {
            int b = w * 8 + i * 4 + lrow;
            ldrow(Hp, b, c, (uint32_t)(buf * STAGEF + BOFFT + b * APITCH + akk));
        }
    };

    float acc[2][4][4];
    #pragma unroll
    for (int i = 0; i < 2; i++)
        #pragma unroll
        for (int j = 0; j < 4; j++)
            #pragma unroll
            for (int r = 0; r < 4; r++) acc[i][j][r] = 0.f;

    loadA(0, 0); loadB(0, 0); cp_commit();
    loadA(1, 1); loadB(1, 1); cp_commit();

    const int g = lane >> 2, tig = lane & 3;
    const uint32_t a_base = smb + (uint32_t)((w * 32 + g) * APITCH + 2 * tig) * 4;
    const uint32_t b_base = smb + (uint32_t)(BOFFT + g * APITCH + 2 * tig) * 4;
    const uint32_t R8 = 8 * APITCH * 4;
    const uint32_t R16 = 16 * APITCH * 4;

    for (int c = 0; c < NCH; c++) {
        cp_wait1();
        __syncthreads();
        const uint32_t bsel = (uint32_t)(c & 1) * (STAGEF * 4);

        #pragma unroll
        for (int ks = 0; ks < 2; ks++) {
            const uint32_t ko = (uint32_t)ks * 64;
            uint32_t bh[4][2], bl[4][2];
            #pragma unroll
            for (int j = 0; j < 4; j++) {
                uint32_t ba = b_base + bsel + (uint32_t)j * R8 + ko;
                float v0x, v0y, v1x, v1y;
                LDS64(v0x, v0y, ba);
                LDS64(v1x, v1y, ba + 32);
                bfsplit(v0x, v0y, bh[j][0], bl[j][0]);
                bfsplit(v1x, v1y, bh[j][1], bl[j][1]);
            }
            #pragma unroll
            for (int i = 0; i < 2; i++) {
                uint32_t aa = a_base + bsel + (uint32_t)i * R16 + ko;
                float v0x, v0y, v1x, v1y, v2x, v2y, v3x, v3y;
                LDS64(v0x, v0y, aa);
                LDS64(v1x, v1y, aa + R8);
                LDS64(v2x, v2y, aa + 32);
                LDS64(v3x, v3y, aa + R8 + 32);
                uint32_t ah0, ah1, ah2, ah3, al0, al1, al2, al3;
                bfsplit(v0x, v0y, ah0, al0);
                bfsplit(v1x, v1y, ah1, al1);
                bfsplit(v2x, v2y, ah2, al2);
                bfsplit(v3x, v3y, ah3, al3);
                #pragma unroll
                for (int j = 0; j < 4; j++) {
                    MMA16816(acc[i][j], ah0, ah1, ah2, ah3, bh[j][0], bh[j][1]);
                    MMA16816(acc[i][j], ah0, ah1, ah2, ah3, bl[j][0], bl[j][1]);
                    MMA16816(acc[i][j], al0, al1, al2, al3, bh[j][0], bh[j][1]);
                }
            }
        }
        __syncthreads();
        if (c + 2 < NCH) { loadA(c + 2, c & 1); loadB(c + 2, c & 1); }
        cp_commit();
    }

    // write partials: D[m=w-row][n=b] -> zp[b*WWID + wrow]
    float* zp = g_zp + (size_t)(p * 8 + s) * BB * WWID;
    const int tc = lane & 3;
    #pragma unroll
    for (int i = 0; i < 2; i++) {
        #pragma unroll
        for (int r = 0; r < 2; r++) {
            int wr = w * 32 + i * 16 + r * 8 + g;
            #pragma unroll
            for (int j = 0; j < 4; j++) {
                #pragma unroll
                for (int cc = 0; cc < 2; cc++) {
                    int b = j * 8 + tc * 2 + cc;
                    zp[b * WWID + wr] = acc[i][j][r * 2 + cc];
                }
            }
        }
    }
}

// ========== kernel 4: reduce partials + bias + relu + weighted gather ==========
__global__ void k_wx(const float* __restrict__ x, const float* __restrict__ b3) {
    const int p = blockIdx.x, b = blockIdx.y, w = threadIdx.x;
    const int lane = w & 31, wrp = w >> 5;
    __shared__ float red[32];
    float z = b3[p * WWID + w];
    #pragma unroll
    for (int s = 0; s < 8; s++)
        z += g_zp[((size_t)(p * 8 + s) * BB + b) * WWID + w];
    z = z > 0.f ? z : 0.f;
    const float4* xr = (const float4*)(x + ((size_t)b * NNODE + p * WWID + w) * DDIM);
    float4 xa = xr[0], xb = xr[1];
    float v[8] = {z * xa.x, z * xa.y, z * xa.z, z * xa.w,
                  z * xb.x, z * xb.y, z * xb.z, z * xb.w};
    #pragma unroll
    for (int d = 0; d < 8; d++)
        #pragma unroll
        for (int o = 16; o > 0; o >>= 1) v[d] += __shfl_xor_sync(0xffffffffu, v[d], o);
    if (lane < 8) red[wrp * 8 + lane] = v[lane];
    __syncthreads();
    if (w < 8)
        g_wx[((size_t)b * PPART + p) * DDIM + w] =
            red[w] + red[8 + w] + red[16 + w] + red[24 + w];
}

// ========== kernel 5: conv + leaky 0.02 ==========
__global__ void k_y(const float* __restrict__ cw, const float* __restrict__ cb,
                    float* __restrict__ out) {
    const int b = blockIdx.x, l = threadIdx.x;
    const float* wxb = g_wx + (size_t)b * PPART * DDIM;
    float acc = cb[l];
    #pragma unroll 4
    for (int p = 0; p < PPART; p++)
        #pragma unroll
        for (int d = 0; d < 8; d++)
            acc += wxb[p * DDIM + d] * cw[l * (DDIM * PPART) + d * PPART + p];
    out[b * LL2 + l] = acc > 0.f ? acc : 0.02f * acc;
}

extern "C" void kernel_launch(void* const* d_in, const int* in_sizes, int n_in,
                              void* d_out, int out_size) {
    const float* x    = (const float*)d_in[0];
    const float* t    = (const float*)d_in[1];
    const float* cap  = (const float*)d_in[2];
    // d_in[3] = partition_index (identity; folded into k_wx)
    const float* W0   = (const float*)d_in[4];
    const float* W1   = (const float*)d_in[5];
    const float* b1   = (const float*)d_in[6];
    const float* W2   = (const float*)d_in[7];
    const float* W3   = (const float*)d_in[8];
    const float* b3   = (const float*)d_in[9];
    const float* cw   = (const float*)d_in[10];
    const float* cb   = (const float*)d_in[11];
    const int* nodes  = (const int*)d_in[12];
    float* out = (float*)d_out;

    const int dsm = 2 * STAGEF * 4;   // 51200 B
    cudaFuncSetAttribute(k_main_bf16s, cudaFuncAttributeMaxDynamicSharedMemorySize, dsm);
    cudaFuncSetAttribute(k_z_mma, cudaFuncAttributeMaxDynamicSharedMemorySize, dsm);

    k_base<<<(PPART * I2D + 7) / 8, 256>>>(W2, b1, cap);
    k_main_bf16s<<<dim3(19, PPART), 128, dsm>>>(W0, x, t, W1, nodes);
    k_z_mma<<<dim3(8, PPART), 128, dsm>>>(W3);
    k_wx<<<dim3(PPART, BB), 128>>>(x, b3);
    k_y<<<BB, LL2>>>(cw, cb, out);
}